// round 16
// baseline (speedup 1.0000x reference)
#include <cuda_runtime.h>
#include <cuda_fp16.h>
#include <math.h>
#include <stdint.h>

#define B_    2
#define N_    4096
#define DIM_  768
#define H_    12
#define HD_   64
#define TOK   (B_ * N_)          // 8192
#define QKVN  (3 * DIM_)         // 2304

// 0.125 * log2(e): folded into Q so softmax = exp2(S)
#define QSCALE 0.18033688011112042f
#define ONES_H2 0x3C003C00u      // fp16x2 {1.0, 1.0}

// Scratch (allocation-free rule: __device__ globals)
__device__ __half g_xh    [(size_t)TOK * DIM_];        // x, fp16 [row][k]
__device__ __half g_wqkvh [(size_t)DIM_ * QKVN];       // w_qkv fp16 [k][n]
__device__ __half g_wprojh[(size_t)DIM_ * DIM_];       // w_proj fp16 [k][n]
__device__ __half g_Qh[(size_t)B_ * H_ * N_ * HD_];    // [b,h,n,d] fp16, pre-scaled
__device__ __half g_Kh[(size_t)B_ * H_ * N_ * HD_];    // [b,h,n,d] fp16
__device__ __half g_Vh[(size_t)B_ * H_ * N_ * HD_];    // [b,h,n,d] fp16 (row-major)
__device__ __half g_att[(size_t)TOK * DIM_];           // [token, h*64+d] fp16

// ---------------------------------------------------------------------------
__device__ __forceinline__ void mma_f16(float c[4], const uint32_t a[4],
                                        uint32_t b0, uint32_t b1) {
    asm volatile(
        "mma.sync.aligned.m16n8k16.row.col.f32.f16.f16.f32 "
        "{%0,%1,%2,%3}, {%4,%5,%6,%7}, {%8,%9}, {%0,%1,%2,%3};"
        : "+f"(c[0]), "+f"(c[1]), "+f"(c[2]), "+f"(c[3])
        : "r"(a[0]), "r"(a[1]), "r"(a[2]), "r"(a[3]), "r"(b0), "r"(b1));
}
__device__ __forceinline__ void ldsm4(uint32_t r[4], uint32_t addr) {
    asm volatile("ldmatrix.sync.aligned.m8n8.x4.shared.b16 {%0,%1,%2,%3}, [%4];"
        : "=r"(r[0]), "=r"(r[1]), "=r"(r[2]), "=r"(r[3]) : "r"(addr));
}
__device__ __forceinline__ void ldsm4t(uint32_t r[4], uint32_t addr) {
    asm volatile("ldmatrix.sync.aligned.m8n8.x4.trans.shared.b16 {%0,%1,%2,%3}, [%4];"
        : "=r"(r[0]), "=r"(r[1]), "=r"(r[2]), "=r"(r[3]) : "r"(addr));
}
__device__ __forceinline__ uint32_t exp2_pack(float a, float b) {
    __half2 r = h2exp2(__floats2half2_rn(a, b));
    return *(uint32_t*)&r;
}
#define CP_ASYNC16(dst, src) \
    asm volatile("cp.async.cg.shared.global [%0], [%1], 16;" :: "r"(dst), "l"(src) : "memory")
#define CP_COMMIT() asm volatile("cp.async.commit_group;" ::: "memory")
template <int n>
__device__ __forceinline__ void cp_wait() {
    asm volatile("cp.async.wait_group %0;" :: "n"(n) : "memory");
}

// ---------------------------------------------------------------------------
// Setup: elementwise fp32 -> fp16 of x, w_qkv, w_proj (proven).
// ---------------------------------------------------------------------------
#define NX4 (TOK * DIM_ / 4)
#define NQ4 (DIM_ * QKVN / 4)
#define NP4 (DIM_ * DIM_ / 4)
#define NSETUP4 (NX4 + NQ4 + NP4)

__global__ void setup_h(const float4* __restrict__ x,
                        const float4* __restrict__ wq,
                        const float4* __restrict__ wp)
{
    const int i = blockIdx.x * blockDim.x + threadIdx.x;
    float4 v;
    __half* dst;
    if (i < NX4)            { v = x[i];              dst = g_xh     + 4 * (size_t)i; }
    else if (i < NX4 + NQ4) { v = wq[i - NX4];       dst = g_wqkvh  + 4 * (size_t)(i - NX4); }
    else if (i < NSETUP4)   { v = wp[i - NX4 - NQ4]; dst = g_wprojh + 4 * (size_t)(i - NX4 - NQ4); }
    else return;
    *(__half2*)(dst)     = __floats2half2_rn(v.x, v.y);
    *(__half2*)(dst + 2) = __floats2half2_rn(v.z, v.w);
}

// ---------------------------------------------------------------------------
// fp16 tensor-core GEMM: 128x128 tile, BK=32, 8 warps, cp.async 3-STAGE
// circular pipeline (2 stages in flight covers L2/DRAM latency).
// MODE 0: A=g_xh, B=g_wqkvh, scatter QKV. MODE 1: A=g_att, B=g_wprojh -> C.
// ---------------------------------------------------------------------------
#define AROWB 80
#define BROWB 272
#define ASTG_B (128 * AROWB)        // 10240 B
#define BSTG_B (32 * BROWB)         //  8704 B

template <int MODE>
__global__ __launch_bounds__(256, 2)
void gemm_h(const float* __restrict__ bias, float* __restrict__ C,
            int M, int Nn, int K)
{
    __shared__ __align__(16) char sA[3][ASTG_B];
    __shared__ __align__(16) char sB[3][BSTG_B];

    const __half* A  = (MODE == 0) ? g_xh : g_att;
    const __half* Bm = (MODE == 0) ? g_wqkvh : g_wprojh;

    const int tid  = threadIdx.x;
    const int wid  = tid >> 5;
    const int lane = tid & 31;
    const int g = lane >> 2;
    const int t = lane & 3;
    const int bm = blockIdx.y * 128;
    const int bn = blockIdx.x * 128;
    const int mw = (wid & 3) * 32;
    const int nw = (wid >> 2) * 64;

    const uint32_t asb = (uint32_t)__cvta_generic_to_shared(&sA[0][0]);
    const uint32_t bsb = (uint32_t)__cvta_generic_to_shared(&sB[0][0]);
    const uint32_t aoff = (lane & 15) * AROWB + (lane >> 4) * 16;
    const uint32_t boff = ((lane & 7) + ((lane >> 3) & 1) * 8) * BROWB + (lane >> 4) * 16;

    const int ar = tid >> 1, aq = (tid & 1) * 2;
    const int br = tid >> 3, bq = (tid & 7) * 2;
    const uint32_t adst = asb + ar * AROWB + aq * 16;
    const uint32_t bdst = bsb + br * BROWB + bq * 16;

    float acc[2][8][4];
    #pragma unroll
    for (int mi = 0; mi < 2; mi++)
        #pragma unroll
        for (int n = 0; n < 8; n++)
            #pragma unroll
            for (int j = 0; j < 4; j++) acc[mi][n][j] = 0.0f;

    const __half* Aptr = A  + (size_t)(bm + ar) * K + aq * 8;
    const __half* Bptr = Bm + (size_t)br * Nn + bn + bq * 8;

    const int nstage = K / 32;
    {   // prologue: stages 0 and 1
        CP_ASYNC16(adst,      Aptr);
        CP_ASYNC16(adst + 16, Aptr + 8);
        CP_ASYNC16(bdst,      Bptr);
        CP_ASYNC16(bdst + 16, Bptr + 8);
        CP_COMMIT();
        const __half* ap = Aptr + 32;
        const __half* bp = Bptr + (size_t)32 * Nn;
        CP_ASYNC16(adst + ASTG_B,      ap);
        CP_ASYNC16(adst + ASTG_B + 16, ap + 8);
        CP_ASYNC16(bdst + BSTG_B,      bp);
        CP_ASYNC16(bdst + BSTG_B + 16, bp + 8);
        CP_COMMIT();
    }

    int buf = 0;        // buffer of stage s
    int nbuf = 2;       // buffer to write stage s+2 into
    #pragma unroll 1
    for (int s = 0; s < nstage; ++s) {
        __syncthreads();   // all warps done reading buffer nbuf (stage s-1)
        if (s + 2 < nstage) {
            const uint32_t oa = nbuf * ASTG_B;
            const uint32_t ob = nbuf * BSTG_B;
            const __half* ap = Aptr + (s + 2) * 32;
            const __half* bp = Bptr + (size_t)(s + 2) * 32 * Nn;
            CP_ASYNC16(adst + oa,      ap);
            CP_ASYNC16(adst + oa + 16, ap + 8);
            CP_ASYNC16(bdst + ob,      bp);
            CP_ASYNC16(bdst + ob + 16, bp + 8);
            CP_COMMIT();
            cp_wait<2>();
        } else if (s + 1 < nstage) {
            cp_wait<1>();
        } else {
            cp_wait<0>();
        }
        __syncthreads();   // stage s visible CTA-wide

        const uint32_t abase = asb + buf * ASTG_B;
        const uint32_t bbase = bsb + buf * BSTG_B;
        #pragma unroll
        for (int kt = 0; kt < 2; kt++) {
            uint32_t af[2][4];
            #pragma unroll
            for (int mi = 0; mi < 2; mi++)
                ldsm4(af[mi], abase + (mw + mi * 16) * AROWB + kt * 32 + aoff);
            #pragma unroll
            for (int np = 0; np < 4; np++) {
                uint32_t bf[4];
                ldsm4t(bf, bbase + kt * 16 * BROWB + (nw + np * 16) * 2 + boff);
                mma_f16(acc[0][2 * np],     af[0], bf[0], bf[1]);
                mma_f16(acc[1][2 * np],     af[1], bf[0], bf[1]);
                mma_f16(acc[0][2 * np + 1], af[0], bf[2], bf[3]);
                mma_f16(acc[1][2 * np + 1], af[1], bf[2], bf[3]);
            }
        }
        buf  = (buf == 2)  ? 0 : buf + 1;
        nbuf = (nbuf == 2) ? 0 : nbuf + 1;
    }

    if (MODE == 1) {
        #pragma unroll
        for (int mi = 0; mi < 2; mi++) {
            const int r0 = bm + mw + mi * 16 + g;
            #pragma unroll
            for (int n = 0; n < 8; n++) {
                const int col = bn + nw + n * 8 + 2 * t;
                const float bb0 = bias[col], bb1 = bias[col + 1];
                *(float2*)(C + (size_t)r0 * Nn + col) =
                    make_float2(acc[mi][n][0] + bb0, acc[mi][n][1] + bb1);
                *(float2*)(C + (size_t)(r0 + 8) * Nn + col) =
                    make_float2(acc[mi][n][2] + bb0, acc[mi][n][3] + bb1);
            }
        }
    } else {
        const int region = (bn + nw) >> 6;
        const int which  = region / H_;
        const int h      = region % H_;
        #pragma unroll
        for (int mi = 0; mi < 2; mi++) {
            #pragma unroll
            for (int jr = 0; jr < 2; jr++) {
                const int row = bm + mw + mi * 16 + g + jr * 8;
                const int b   = row >> 12;
                const int ntk = row & (N_ - 1);
                #pragma unroll
                for (int n = 0; n < 8; n++) {
                    const int dd  = (nw + n * 8 + 2 * t) & 63;
                    const int col = bn + nw + n * 8 + 2 * t;
                    const float v0 = acc[mi][n][jr * 2 + 0] + bias[col];
                    const float v1 = acc[mi][n][jr * 2 + 1] + bias[col + 1];
                    const size_t nd = (((size_t)(b * H_ + h) * N_) + ntk) * HD_ + dd;
                    if (which == 0) {
                        *(__half2*)&g_Qh[nd] = __floats2half2_rn(v0 * QSCALE, v1 * QSCALE);
                    } else if (which == 1) {
                        *(__half2*)&g_Kh[nd] = __floats2half2_rn(v0, v1);
                    } else {
                        *(__half2*)&g_Vh[nd] = __floats2half2_rn(v0, v1);
                    }
                }
            }
        }
    }
}

// ---------------------------------------------------------------------------
// Flash attention (round-15 proven): full fp16 mma, fp32 accumulate,
// register-direct P, 128-key tiles, 2-stage cp.async.
// ---------------------------------------------------------------------------
#define ROWB 144
#define KTILE_B (128 * ROWB)            // 18432 B
#define VTILE_B (128 * ROWB)            // 18432 B
#define BUF_B   (KTILE_B + VTILE_B)     // 36864 B
#define ATTN_SMEM_BYTES (2 * BUF_B)     // 73728 B

__global__ __launch_bounds__(256, 2)
void attn_mma_kernel()
{
    extern __shared__ __align__(16) float sm[];
    const uint32_t sb = (uint32_t)__cvta_generic_to_shared(sm);

    const int tid  = threadIdx.x;
    const int wid  = tid >> 5;
    const int lane = tid & 31;
    const int g = lane >> 2;
    const int t = lane & 3;
    const int g4 = lane >> 3;

    const int h = blockIdx.y, b = blockIdx.z;
    const int m0 = blockIdx.x * 128;
    const size_t hb = (size_t)(b * H_ + h) * N_ * HD_;

    const __half* Kg = g_Kh + hb;
    const __half* Vg = g_Vh + hb;

    const uint32_t bfoff = ((lane & 7) + ((g4 >> 1) << 3)) * ROWB + (g4 & 1) * 16;
    const uint32_t vtoff = ((lane & 7) + ((lane >> 3) & 1) * 8) * ROWB + (lane >> 4) * 16;

    const __half* Qg = g_Qh + hb + (size_t)(m0 + wid * 16) * HD_;
    uint32_t qa[4][4];
    #pragma unroll
    for (int dc = 0; dc < 4; dc++) {
        qa[dc][0] = *(const uint32_t*)(Qg + (size_t)g * HD_       + dc * 16 + 2 * t);
        qa[dc][1] = *(const uint32_t*)(Qg + (size_t)(g + 8) * HD_ + dc * 16 + 2 * t);
        qa[dc][2] = *(const uint32_t*)(Qg + (size_t)g * HD_       + dc * 16 + 2 * t + 8);
        qa[dc][3] = *(const uint32_t*)(Qg + (size_t)(g + 8) * HD_ + dc * 16 + 2 * t + 8);
    }

    float oacc[8][4];
    #pragma unroll
    for (int n = 0; n < 8; n++)
        #pragma unroll
        for (int j = 0; j < 4; j++) oacc[n][j] = 0.0f;
    float lacc[4] = {0.0f, 0.0f, 0.0f, 0.0f};

    {   // prefetch tile 0
        #pragma unroll
        for (int i = 0; i < 4; i++) {
            const int c = tid + i * 256;
            const int r = c >> 3, q = c & 7;
            CP_ASYNC16(sb + r * ROWB + q * 16, Kg + (size_t)r * HD_ + q * 8);
            CP_ASYNC16(sb + KTILE_B + r * ROWB + q * 16, Vg + (size_t)r * HD_ + q * 8);
        }
        CP_COMMIT();
    }

    #pragma unroll 1
    for (int it = 0; it < 32; ++it) {
        __syncthreads();

        if (it + 1 < 32) {
            const uint32_t bo = ((it + 1) & 1) * BUF_B;
            const __half* Kt = Kg + (size_t)((it + 1) * 128) * HD_;
            const __half* Vt = Vg + (size_t)((it + 1) * 128) * HD_;
            #pragma unroll
            for (int i = 0; i < 4; i++) {
                const int c = tid + i * 256;
                const int r = c >> 3, q = c & 7;
                CP_ASYNC16(sb + bo + r * ROWB + q * 16, Kt + (size_t)r * HD_ + q * 8);
                CP_ASYNC16(sb + bo + KTILE_B + r * ROWB + q * 16, Vt + (size_t)r * HD_ + q * 8);
            }
            CP_COMMIT();
            cp_wait<1>();
        } else {
            cp_wait<0>();
        }
        __syncthreads();

        const uint32_t ksb = sb + (it & 1) * BUF_B;
        const uint32_t kla = ksb + bfoff;
        const uint32_t vla = ksb + KTILE_B + vtoff;

        #pragma unroll
        for (int nc = 0; nc < 8; nc++) {
            float sacc[2][4];
            #pragma unroll
            for (int j = 0; j < 4; j++) { sacc[0][j] = 0.0f; sacc[1][j] = 0.0f; }

            #pragma unroll
            for (int dc = 0; dc < 4; dc++) {
                uint32_t f[4];
                ldsm4(f, kla + nc * (16 * ROWB) + dc * 32);
                mma_f16(sacc[0], qa[dc], f[0], f[1]);
                mma_f16(sacc[1], qa[dc], f[2], f[3]);
            }

            uint32_t pa[4];
            pa[0] = exp2_pack(sacc[0][0], sacc[0][1]);
            pa[1] = exp2_pack(sacc[0][2], sacc[0][3]);
            pa[2] = exp2_pack(sacc[1][0], sacc[1][1]);
            pa[3] = exp2_pack(sacc[1][2], sacc[1][3]);
            mma_f16(lacc, pa, ONES_H2, ONES_H2);

            #pragma unroll
            for (int jp = 0; jp < 4; jp++) {
                uint32_t f[4];
                ldsm4t(f, vla + nc * (16 * ROWB) + jp * 32);
                mma_f16(oacc[2 * jp],     pa, f[0], f[1]);
                mma_f16(oacc[2 * jp + 1], pa, f[2], f[3]);
            }
        }
    }

    const float inv0 = 1.0f / lacc[0];
    const float inv1 = 1.0f / lacc[2];

    const size_t row0 = (size_t)(b * N_ + m0 + wid * 16 + g);
    __half* o0 = g_att + row0 * DIM_ + h * HD_;
    __half* o1 = o0 + 8 * DIM_;
    #pragma unroll
    for (int n = 0; n < 8; n++) {
        *(__half2*)(o0 + n * 8 + 2 * t) =
            __floats2half2_rn(oacc[n][0] * inv0, oacc[n][1] * inv0);
        *(__half2*)(o1 + n * 8 + 2 * t) =
            __floats2half2_rn(oacc[n][2] * inv1, oacc[n][3] * inv1);
    }
}

// ---------------------------------------------------------------------------
extern "C" void kernel_launch(void* const* d_in, const int* in_sizes, int n_in,
                              void* d_out, int out_size)
{
    const float* x      = (const float*)d_in[0];
    const float* w_qkv  = (const float*)d_in[1];
    const float* b_qkv  = (const float*)d_in[2];
    const float* w_proj = (const float*)d_in[3];
    const float* b_proj = (const float*)d_in[4];
    float* out = (float*)d_out;

    cudaFuncSetAttribute(attn_mma_kernel,
                         cudaFuncAttributeMaxDynamicSharedMemorySize, ATTN_SMEM_BYTES);

    {   // 0) fp32 -> fp16 of x / w_qkv / w_proj
        setup_h<<<NSETUP4 / 256, 256>>>((const float4*)x,
                                        (const float4*)w_qkv,
                                        (const float4*)w_proj);
    }
    {   // 1) QKV GEMM (fp16 mma, 3-stage cp.async) + head-major scatter
        dim3 grid(QKVN / 128, TOK / 128);
        gemm_h<0><<<grid, 256>>>(b_qkv, nullptr, TOK, QKVN, DIM_);
    }
    {   // 2) attention: fp16 mma, register-direct P, 128-key tiles
        dim3 grid(N_ / 128, H_, B_);
        attn_mma_kernel<<<grid, 256, ATTN_SMEM_BYTES>>>();
    }
    {   // 3) output projection (fp16 mma, 3-stage cp.async)
        dim3 grid(DIM_ / 128, TOK / 128);
        gemm_h<1><<<grid, 256>>>(b_proj, out, TOK, DIM_, DIM_);
    }
}

// round 17
// speedup vs baseline: 1.0204x; 1.0204x over previous
#include <cuda_runtime.h>
#include <cuda_fp16.h>
#include <math.h>
#include <stdint.h>

#define B_    2
#define N_    4096
#define DIM_  768
#define H_    12
#define HD_   64
#define TOK   (B_ * N_)          // 8192
#define QKVN  (3 * DIM_)         // 2304

// 0.125 * log2(e): folded into Q so softmax = exp2(S)
#define QSCALE 0.18033688011112042f
#define ONES_H2 0x3C003C00u      // fp16x2 {1.0, 1.0}

// Scratch (allocation-free rule: __device__ globals)
__device__ __half g_xh    [(size_t)TOK * DIM_];        // x, fp16 [row][k]
__device__ __half g_wqkvh [(size_t)DIM_ * QKVN];       // w_qkv fp16 [k][n]
__device__ __half g_wprojh[(size_t)DIM_ * DIM_];       // w_proj fp16 [k][n]
__device__ __half g_Qh[(size_t)B_ * H_ * N_ * HD_];    // [b,h,n,d] fp16, pre-scaled
__device__ __half g_Kh[(size_t)B_ * H_ * N_ * HD_];    // [b,h,n,d] fp16
__device__ __half g_Vh[(size_t)B_ * H_ * N_ * HD_];    // [b,h,n,d] fp16 (row-major)
__device__ __half g_att[(size_t)TOK * DIM_];           // [token, h*64+d] fp16

// ---------------------------------------------------------------------------
__device__ __forceinline__ void mma_f16(float c[4], const uint32_t a[4],
                                        uint32_t b0, uint32_t b1) {
    asm volatile(
        "mma.sync.aligned.m16n8k16.row.col.f32.f16.f16.f32 "
        "{%0,%1,%2,%3}, {%4,%5,%6,%7}, {%8,%9}, {%0,%1,%2,%3};"
        : "+f"(c[0]), "+f"(c[1]), "+f"(c[2]), "+f"(c[3])
        : "r"(a[0]), "r"(a[1]), "r"(a[2]), "r"(a[3]), "r"(b0), "r"(b1));
}
__device__ __forceinline__ void ldsm4(uint32_t r[4], uint32_t addr) {
    asm volatile("ldmatrix.sync.aligned.m8n8.x4.shared.b16 {%0,%1,%2,%3}, [%4];"
        : "=r"(r[0]), "=r"(r[1]), "=r"(r[2]), "=r"(r[3]) : "r"(addr));
}
__device__ __forceinline__ void ldsm4t(uint32_t r[4], uint32_t addr) {
    asm volatile("ldmatrix.sync.aligned.m8n8.x4.trans.shared.b16 {%0,%1,%2,%3}, [%4];"
        : "=r"(r[0]), "=r"(r[1]), "=r"(r[2]), "=r"(r[3]) : "r"(addr));
}
__device__ __forceinline__ uint32_t exp2_pack(float a, float b) {
    __half2 r = h2exp2(__floats2half2_rn(a, b));
    return *(uint32_t*)&r;
}
#define CP_ASYNC16(dst, src) \
    asm volatile("cp.async.cg.shared.global [%0], [%1], 16;" :: "r"(dst), "l"(src) : "memory")
#define CP_COMMIT() asm volatile("cp.async.commit_group;" ::: "memory")
template <int n>
__device__ __forceinline__ void cp_wait() {
    asm volatile("cp.async.wait_group %0;" :: "n"(n) : "memory");
}

// ---------------------------------------------------------------------------
// Setup: elementwise fp32 -> fp16 of x, w_qkv, w_proj (proven).
// ---------------------------------------------------------------------------
#define NX4 (TOK * DIM_ / 4)
#define NQ4 (DIM_ * QKVN / 4)
#define NP4 (DIM_ * DIM_ / 4)
#define NSETUP4 (NX4 + NQ4 + NP4)

__global__ void setup_h(const float4* __restrict__ x,
                        const float4* __restrict__ wq,
                        const float4* __restrict__ wp)
{
    const int i = blockIdx.x * blockDim.x + threadIdx.x;
    float4 v;
    __half* dst;
    if (i < NX4)            { v = x[i];              dst = g_xh     + 4 * (size_t)i; }
    else if (i < NX4 + NQ4) { v = wq[i - NX4];       dst = g_wqkvh  + 4 * (size_t)(i - NX4); }
    else if (i < NSETUP4)   { v = wp[i - NX4 - NQ4]; dst = g_wprojh + 4 * (size_t)(i - NX4 - NQ4); }
    else return;
    *(__half2*)(dst)     = __floats2half2_rn(v.x, v.y);
    *(__half2*)(dst + 2) = __floats2half2_rn(v.z, v.w);
}

// ---------------------------------------------------------------------------
// fp16 tensor-core GEMM: 128x128 tile, BK=32, 8 warps, cp.async 4-STAGE
// circular pipeline with ONE __syncthreads per stage (CUTLASS multistage
// ordering: wait<2> -> sync -> issue s+3 -> compute s).
// MODE 0: A=g_xh, B=g_wqkvh, scatter QKV. MODE 1: A=g_att, B=g_wprojh -> C.
// ---------------------------------------------------------------------------
#define AROWB 80
#define BROWB 272
#define ASTG_B (128 * AROWB)        // 10240 B
#define BSTG_B (32 * BROWB)         //  8704 B
#define GEMM_SMEM_BYTES (4 * (ASTG_B + BSTG_B))   // 75776 B (dynamic)

template <int MODE>
__global__ __launch_bounds__(256, 2)
void gemm_h(const float* __restrict__ bias, float* __restrict__ C,
            int M, int Nn, int K)
{
    extern __shared__ __align__(16) char gsm[];
    // layout: A buffers [0, 4*ASTG_B), B buffers [4*ASTG_B, 4*(ASTG_B+BSTG_B))
    const uint32_t asb = (uint32_t)__cvta_generic_to_shared(gsm);
    const uint32_t bsb = asb + 4 * ASTG_B;

    const __half* A  = (MODE == 0) ? g_xh : g_att;
    const __half* Bm = (MODE == 0) ? g_wqkvh : g_wprojh;

    const int tid  = threadIdx.x;
    const int wid  = tid >> 5;
    const int lane = tid & 31;
    const int g = lane >> 2;
    const int t = lane & 3;
    const int bm = blockIdx.y * 128;
    const int bn = blockIdx.x * 128;
    const int mw = (wid & 3) * 32;
    const int nw = (wid >> 2) * 64;

    const uint32_t aoff = (lane & 15) * AROWB + (lane >> 4) * 16;
    const uint32_t boff = ((lane & 7) + ((lane >> 3) & 1) * 8) * BROWB + (lane >> 4) * 16;

    const int ar = tid >> 1, aq = (tid & 1) * 2;
    const int br = tid >> 3, bq = (tid & 7) * 2;
    const uint32_t adst = asb + ar * AROWB + aq * 16;
    const uint32_t bdst = bsb + br * BROWB + bq * 16;

    float acc[2][8][4];
    #pragma unroll
    for (int mi = 0; mi < 2; mi++)
        #pragma unroll
        for (int n = 0; n < 8; n++)
            #pragma unroll
            for (int j = 0; j < 4; j++) acc[mi][n][j] = 0.0f;

    const __half* Aptr = A  + (size_t)(bm + ar) * K + aq * 8;
    const __half* Bptr = Bm + (size_t)br * Nn + bn + bq * 8;

    const int nstage = K / 32;
    {   // prologue: stages 0, 1, 2
        #pragma unroll
        for (int p = 0; p < 3; p++) {
            const __half* ap = Aptr + p * 32;
            const __half* bp = Bptr + (size_t)p * 32 * Nn;
            CP_ASYNC16(adst + p * ASTG_B,      ap);
            CP_ASYNC16(adst + p * ASTG_B + 16, ap + 8);
            CP_ASYNC16(bdst + p * BSTG_B,      bp);
            CP_ASYNC16(bdst + p * BSTG_B + 16, bp + 8);
            CP_COMMIT();
        }
    }

    int buf = 0;    // buffer of stage s
    int wbuf = 3;   // buffer for stage s+3
    #pragma unroll 1
    for (int s = 0; s < nstage; ++s) {
        cp_wait<2>();       // stage s landed (this warp's groups)
        __syncthreads();    // stage s CTA-visible; compute(s-1) done CTA-wide

        if (s + 3 < nstage) {
            const __half* ap = Aptr + (s + 3) * 32;
            const __half* bp = Bptr + (size_t)(s + 3) * 32 * Nn;
            CP_ASYNC16(adst + wbuf * ASTG_B,      ap);
            CP_ASYNC16(adst + wbuf * ASTG_B + 16, ap + 8);
            CP_ASYNC16(bdst + wbuf * BSTG_B,      bp);
            CP_ASYNC16(bdst + wbuf * BSTG_B + 16, bp + 8);
        }
        CP_COMMIT();        // always commit (empty groups keep count uniform)

        const uint32_t abase = asb + buf * ASTG_B;
        const uint32_t bbase = bsb + buf * BSTG_B;
        #pragma unroll
        for (int kt = 0; kt < 2; kt++) {
            uint32_t af[2][4];
            #pragma unroll
            for (int mi = 0; mi < 2; mi++)
                ldsm4(af[mi], abase + (mw + mi * 16) * AROWB + kt * 32 + aoff);
            #pragma unroll
            for (int np = 0; np < 4; np++) {
                uint32_t bf[4];
                ldsm4t(bf, bbase + kt * 16 * BROWB + (nw + np * 16) * 2 + boff);
                mma_f16(acc[0][2 * np],     af[0], bf[0], bf[1]);
                mma_f16(acc[1][2 * np],     af[1], bf[0], bf[1]);
                mma_f16(acc[0][2 * np + 1], af[0], bf[2], bf[3]);
                mma_f16(acc[1][2 * np + 1], af[1], bf[2], bf[3]);
            }
        }
        buf  = (buf == 3)  ? 0 : buf + 1;
        wbuf = (wbuf == 3) ? 0 : wbuf + 1;
    }

    if (MODE == 1) {
        #pragma unroll
        for (int mi = 0; mi < 2; mi++) {
            const int r0 = bm + mw + mi * 16 + g;
            #pragma unroll
            for (int n = 0; n < 8; n++) {
                const int col = bn + nw + n * 8 + 2 * t;
                const float bb0 = bias[col], bb1 = bias[col + 1];
                *(float2*)(C + (size_t)r0 * Nn + col) =
                    make_float2(acc[mi][n][0] + bb0, acc[mi][n][1] + bb1);
                *(float2*)(C + (size_t)(r0 + 8) * Nn + col) =
                    make_float2(acc[mi][n][2] + bb0, acc[mi][n][3] + bb1);
            }
        }
    } else {
        const int region = (bn + nw) >> 6;
        const int which  = region / H_;
        const int h      = region % H_;
        #pragma unroll
        for (int mi = 0; mi < 2; mi++) {
            #pragma unroll
            for (int jr = 0; jr < 2; jr++) {
                const int row = bm + mw + mi * 16 + g + jr * 8;
                const int b   = row >> 12;
                const int ntk = row & (N_ - 1);
                #pragma unroll
                for (int n = 0; n < 8; n++) {
                    const int dd  = (nw + n * 8 + 2 * t) & 63;
                    const int col = bn + nw + n * 8 + 2 * t;
                    const float v0 = acc[mi][n][jr * 2 + 0] + bias[col];
                    const float v1 = acc[mi][n][jr * 2 + 1] + bias[col + 1];
                    const size_t nd = (((size_t)(b * H_ + h) * N_) + ntk) * HD_ + dd;
                    if (which == 0) {
                        *(__half2*)&g_Qh[nd] = __floats2half2_rn(v0 * QSCALE, v1 * QSCALE);
                    } else if (which == 1) {
                        *(__half2*)&g_Kh[nd] = __floats2half2_rn(v0, v1);
                    } else {
                        *(__half2*)&g_Vh[nd] = __floats2half2_rn(v0, v1);
                    }
                }
            }
        }
    }
}

// ---------------------------------------------------------------------------
// Flash attention (round-15 proven, unchanged): full fp16 mma, fp32 acc,
// register-direct P, 128-key tiles, 2-stage cp.async.
// ---------------------------------------------------------------------------
#define ROWB 144
#define KTILE_B (128 * ROWB)            // 18432 B
#define VTILE_B (128 * ROWB)            // 18432 B
#define BUF_B   (KTILE_B + VTILE_B)     // 36864 B
#define ATTN_SMEM_BYTES (2 * BUF_B)     // 73728 B

__global__ __launch_bounds__(256, 2)
void attn_mma_kernel()
{
    extern __shared__ __align__(16) float sm[];
    const uint32_t sb = (uint32_t)__cvta_generic_to_shared(sm);

    const int tid  = threadIdx.x;
    const int wid  = tid >> 5;
    const int lane = tid & 31;
    const int g = lane >> 2;
    const int t = lane & 3;
    const int g4 = lane >> 3;

    const int h = blockIdx.y, b = blockIdx.z;
    const int m0 = blockIdx.x * 128;
    const size_t hb = (size_t)(b * H_ + h) * N_ * HD_;

    const __half* Kg = g_Kh + hb;
    const __half* Vg = g_Vh + hb;

    const uint32_t bfoff = ((lane & 7) + ((g4 >> 1) << 3)) * ROWB + (g4 & 1) * 16;
    const uint32_t vtoff = ((lane & 7) + ((lane >> 3) & 1) * 8) * ROWB + (lane >> 4) * 16;

    const __half* Qg = g_Qh + hb + (size_t)(m0 + wid * 16) * HD_;
    uint32_t qa[4][4];
    #pragma unroll
    for (int dc = 0; dc < 4; dc++) {
        qa[dc][0] = *(const uint32_t*)(Qg + (size_t)g * HD_       + dc * 16 + 2 * t);
        qa[dc][1] = *(const uint32_t*)(Qg + (size_t)(g + 8) * HD_ + dc * 16 + 2 * t);
        qa[dc][2] = *(const uint32_t*)(Qg + (size_t)g * HD_       + dc * 16 + 2 * t + 8);
        qa[dc][3] = *(const uint32_t*)(Qg + (size_t)(g + 8) * HD_ + dc * 16 + 2 * t + 8);
    }

    float oacc[8][4];
    #pragma unroll
    for (int n = 0; n < 8; n++)
        #pragma unroll
        for (int j = 0; j < 4; j++) oacc[n][j] = 0.0f;
    float lacc[4] = {0.0f, 0.0f, 0.0f, 0.0f};

    {   // prefetch tile 0
        #pragma unroll
        for (int i = 0; i < 4; i++) {
            const int c = tid + i * 256;
            const int r = c >> 3, q = c & 7;
            CP_ASYNC16(sb + r * ROWB + q * 16, Kg + (size_t)r * HD_ + q * 8);
            CP_ASYNC16(sb + KTILE_B + r * ROWB + q * 16, Vg + (size_t)r * HD_ + q * 8);
        }
        CP_COMMIT();
    }

    #pragma unroll 1
    for (int it = 0; it < 32; ++it) {
        __syncthreads();

        if (it + 1 < 32) {
            const uint32_t bo = ((it + 1) & 1) * BUF_B;
            const __half* Kt = Kg + (size_t)((it + 1) * 128) * HD_;
            const __half* Vt = Vg + (size_t)((it + 1) * 128) * HD_;
            #pragma unroll
            for (int i = 0; i < 4; i++) {
                const int c = tid + i * 256;
                const int r = c >> 3, q = c & 7;
                CP_ASYNC16(sb + bo + r * ROWB + q * 16, Kt + (size_t)r * HD_ + q * 8);
                CP_ASYNC16(sb + bo + KTILE_B + r * ROWB + q * 16, Vt + (size_t)r * HD_ + q * 8);
            }
            CP_COMMIT();
            cp_wait<1>();
        } else {
            cp_wait<0>();
        }
        __syncthreads();

        const uint32_t ksb = sb + (it & 1) * BUF_B;
        const uint32_t kla = ksb + bfoff;
        const uint32_t vla = ksb + KTILE_B + vtoff;

        #pragma unroll
        for (int nc = 0; nc < 8; nc++) {
            float sacc[2][4];
            #pragma unroll
            for (int j = 0; j < 4; j++) { sacc[0][j] = 0.0f; sacc[1][j] = 0.0f; }

            #pragma unroll
            for (int dc = 0; dc < 4; dc++) {
                uint32_t f[4];
                ldsm4(f, kla + nc * (16 * ROWB) + dc * 32);
                mma_f16(sacc[0], qa[dc], f[0], f[1]);
                mma_f16(sacc[1], qa[dc], f[2], f[3]);
            }

            uint32_t pa[4];
            pa[0] = exp2_pack(sacc[0][0], sacc[0][1]);
            pa[1] = exp2_pack(sacc[0][2], sacc[0][3]);
            pa[2] = exp2_pack(sacc[1][0], sacc[1][1]);
            pa[3] = exp2_pack(sacc[1][2], sacc[1][3]);
            mma_f16(lacc, pa, ONES_H2, ONES_H2);

            #pragma unroll
            for (int jp = 0; jp < 4; jp++) {
                uint32_t f[4];
                ldsm4t(f, vla + nc * (16 * ROWB) + jp * 32);
                mma_f16(oacc[2 * jp],     pa, f[0], f[1]);
                mma_f16(oacc[2 * jp + 1], pa, f[2], f[3]);
            }
        }
    }

    const float inv0 = 1.0f / lacc[0];
    const float inv1 = 1.0f / lacc[2];

    const size_t row0 = (size_t)(b * N_ + m0 + wid * 16 + g);
    __half* o0 = g_att + row0 * DIM_ + h * HD_;
    __half* o1 = o0 + 8 * DIM_;
    #pragma unroll
    for (int n = 0; n < 8; n++) {
        *(__half2*)(o0 + n * 8 + 2 * t) =
            __floats2half2_rn(oacc[n][0] * inv0, oacc[n][1] * inv0);
        *(__half2*)(o1 + n * 8 + 2 * t) =
            __floats2half2_rn(oacc[n][2] * inv1, oacc[n][3] * inv1);
    }
}

// ---------------------------------------------------------------------------
extern "C" void kernel_launch(void* const* d_in, const int* in_sizes, int n_in,
                              void* d_out, int out_size)
{
    const float* x      = (const float*)d_in[0];
    const float* w_qkv  = (const float*)d_in[1];
    const float* b_qkv  = (const float*)d_in[2];
    const float* w_proj = (const float*)d_in[3];
    const float* b_proj = (const float*)d_in[4];
    float* out = (float*)d_out;

    cudaFuncSetAttribute(attn_mma_kernel,
                         cudaFuncAttributeMaxDynamicSharedMemorySize, ATTN_SMEM_BYTES);
    cudaFuncSetAttribute(gemm_h<0>,
                         cudaFuncAttributeMaxDynamicSharedMemorySize, GEMM_SMEM_BYTES);
    cudaFuncSetAttribute(gemm_h<1>,
                         cudaFuncAttributeMaxDynamicSharedMemorySize, GEMM_SMEM_BYTES);

    {   // 0) fp32 -> fp16 of x / w_qkv / w_proj
        setup_h<<<NSETUP4 / 256, 256>>>((const float4*)x,
                                        (const float4*)w_qkv,
                                        (const float4*)w_proj);
    }
    {   // 1) QKV GEMM (fp16 mma, 4-stage single-sync cp.async)
        dim3 grid(QKVN / 128, TOK / 128);
        gemm_h<0><<<grid, 256, GEMM_SMEM_BYTES>>>(b_qkv, nullptr, TOK, QKVN, DIM_);
    }
    {   // 2) attention: fp16 mma, register-direct P, 128-key tiles
        dim3 grid(N_ / 128, H_, B_);
        attn_mma_kernel<<<grid, 256, ATTN_SMEM_BYTES>>>();
    }
    {   // 3) output projection (fp16 mma, 4-stage single-sync cp.async)
        dim3 grid(DIM_ / 128, TOK / 128);
        gemm_h<1><<<grid, 256, GEMM_SMEM_BYTES>>>(b_proj, out, TOK, DIM_, DIM_);
    }
}